// round 2
// baseline (speedup 1.0000x reference)
#include <cuda_runtime.h>
#include <cuda_bf16.h>
#include <cstdint>

#define NN      50000
#define EE      800000
#define ETOT    (EE + NN)        // edges + self loops
#define IN_CH   256
#define HIDC    64
#define HEADS   2
#define C1      (HEADS * HIDC)   // 128
#define BN_EPS  1e-5f

// ---------------- scratch (static device arrays; no allocation) --------------
__device__ float g_xl1[NN * C1];
__device__ float g_xr1[NN * C1];
__device__ float g_p1 [ETOT * HEADS];
__device__ float g_sum1[NN * HEADS];
__device__ float g_h1 [NN * C1];     // layer-1 aggregation accumulator
__device__ float g_hm [NN * C1];     // after bn1 + elu
__device__ float g_xl2[NN * HIDC];
__device__ float g_xr2[NN * HIDC];
__device__ float g_p2 [ETOT];
__device__ float g_sum2[NN];
__device__ float g_h2 [NN * HIDC];   // layer-2 aggregation accumulator

// ---------------- helpers ----------------------------------------------------
__device__ __forceinline__ float lrelu(float v) { return v > 0.f ? v : 0.2f * v; }

__device__ __forceinline__ void red_add_v4(float* addr, float4 v) {
    asm volatile("red.global.add.v4.f32 [%0], {%1, %2, %3, %4};"
                 :: "l"(addr), "f"(v.x), "f"(v.y), "f"(v.z), "f"(v.w) : "memory");
}
__device__ __forceinline__ void red_add_v2(float* addr, float2 v) {
    asm volatile("red.global.add.v2.f32 [%0], {%1, %2};"
                 :: "l"(addr), "f"(v.x), "f"(v.y) : "memory");
}

// ---------------- zero accumulators (fresh every launch / graph replay) ------
__global__ void k_zero() {
    int i = blockIdx.x * blockDim.x + threadIdx.x;
    int stride = gridDim.x * blockDim.x;
    for (int j = i; j < NN * C1;    j += stride) g_h1[j]   = 0.f;
    for (int j = i; j < NN * HIDC;  j += stride) g_h2[j]   = 0.f;
    for (int j = i; j < NN * HEADS; j += stride) g_sum1[j] = 0.f;
    for (int j = i; j < NN;         j += stride) g_sum2[j] = 0.f;
}

// ---------------- dual GEMM: outl = X@Wl+bl, outr = X@Wr+br ------------------
// blockDim = 2*M threads, 32-row tile. Thread (mat = t/M, col = t%M) computes
// 32 rows of one output column. X tile staged in smem, W streamed from L2.
template<int K, int M>
__device__ __forceinline__ void dual_gemm_body(
    const float* __restrict__ X,
    const float* __restrict__ Wl, const float* __restrict__ bl,
    const float* __restrict__ Wr, const float* __restrict__ br,
    float* __restrict__ outl, float* __restrict__ outr, int n)
{
    __shared__ float xs[32][K];
    const int t  = threadIdx.x;
    const int r0 = blockIdx.x * 32;

    // stage X tile (zero-pad OOB rows)
    for (int i = t * 4; i < 32 * K; i += 2 * M * 4) {
        int row = i / K, kk = i % K;
        float4 v = make_float4(0.f, 0.f, 0.f, 0.f);
        if (r0 + row < n) v = *(const float4*)&X[(size_t)(r0 + row) * K + kk];
        *(float4*)&xs[row][kk] = v;
    }
    __syncthreads();

    const int mat = t / M, col = t % M;
    const float* __restrict__ W = mat ? Wr : Wl;
    const float bias = mat ? br[col] : bl[col];

    float acc[32];
#pragma unroll
    for (int r = 0; r < 32; r++) acc[r] = 0.f;

    for (int k = 0; k < K; k += 4) {
        float w0 = W[(k + 0) * M + col];
        float w1 = W[(k + 1) * M + col];
        float w2 = W[(k + 2) * M + col];
        float w3 = W[(k + 3) * M + col];
#pragma unroll
        for (int r = 0; r < 32; r++) {
            float4 xv = *(const float4*)&xs[r][k];
            acc[r] = fmaf(xv.x, w0, acc[r]);
            acc[r] = fmaf(xv.y, w1, acc[r]);
            acc[r] = fmaf(xv.z, w2, acc[r]);
            acc[r] = fmaf(xv.w, w3, acc[r]);
        }
    }

    float* __restrict__ out = mat ? outr : outl;
#pragma unroll
    for (int r = 0; r < 32; r++)
        if (r0 + r < n) out[(size_t)(r0 + r) * M + col] = acc[r] + bias;
}

__global__ void k_gemm1(const float* __restrict__ X,
                        const float* __restrict__ Wl, const float* __restrict__ bl,
                        const float* __restrict__ Wr, const float* __restrict__ br)
{
    dual_gemm_body<IN_CH, C1>(X, Wl, bl, Wr, br, g_xl1, g_xr1, NN);
}

__global__ void k_gemm2(const float* __restrict__ Wl, const float* __restrict__ bl,
                        const float* __restrict__ Wr, const float* __restrict__ br)
{
    dual_gemm_body<C1, HIDC>(g_hm, Wl, bl, Wr, br, g_xl2, g_xr2, NN);
}

// ---------------- layer-1 edge logits + softmax denominator ------------------
// warp per edge; lane handles 4 channels of 128. Softmax max-shift omitted
// (alpha = e^l / sum e^l is shift-invariant; logits are O(1)).
__global__ void k_edge1(const int* __restrict__ ei, const float* __restrict__ att)
{
    int warp = (blockIdx.x * blockDim.x + threadIdx.x) >> 5;
    int lane = threadIdx.x & 31;
    if (warp >= ETOT) return;

    int src, dst;
    if (warp < EE) { src = ei[warp]; dst = ei[EE + warp]; }
    else           { src = dst = warp - EE; }

    int c = lane * 4;
    float4 a  = *(const float4*)&g_xl1[(size_t)src * C1 + c];
    float4 b  = *(const float4*)&g_xr1[(size_t)dst * C1 + c];
    float4 at = *(const float4*)&att[c];   // att1 flattened [H*C] == channel index

    float s = at.x * lrelu(a.x + b.x)
            + at.y * lrelu(a.y + b.y)
            + at.z * lrelu(a.z + b.z)
            + at.w * lrelu(a.w + b.w);

    // reduce within each 16-lane half (one head each)
    s += __shfl_xor_sync(0xffffffffu, s, 8);
    s += __shfl_xor_sync(0xffffffffu, s, 4);
    s += __shfl_xor_sync(0xffffffffu, s, 2);
    s += __shfl_xor_sync(0xffffffffu, s, 1);

    if ((lane & 15) == 0) {
        int h = lane >> 4;
        float p = __expf(s);
        g_p1[(size_t)warp * 2 + h] = p;
        atomicAdd(&g_sum1[(size_t)dst * 2 + h], p);
    }
}

// ---------------- layer-1 weighted aggregation -------------------------------
__global__ void k_aggr1(const int* __restrict__ ei)
{
    int warp = (blockIdx.x * blockDim.x + threadIdx.x) >> 5;
    int lane = threadIdx.x & 31;
    if (warp >= ETOT) return;

    int src, dst;
    if (warp < EE) { src = ei[warp]; dst = ei[EE + warp]; }
    else           { src = dst = warp - EE; }

    int c = lane * 4;
    int h = lane >> 4;
    float alpha = g_p1[(size_t)warp * 2 + h] / g_sum1[(size_t)dst * 2 + h];

    float4 v = *(const float4*)&g_xl1[(size_t)src * C1 + c];
    v.x *= alpha; v.y *= alpha; v.z *= alpha; v.w *= alpha;
    red_add_v4(&g_h1[(size_t)dst * C1 + c], v);
}

// ---------------- layer-1 epilogue: +bias, bn, elu ---------------------------
__global__ void k_epi1(const float* __restrict__ bias,
                       const float* __restrict__ bg, const float* __restrict__ bb,
                       const float* __restrict__ bm, const float* __restrict__ bv)
{
    int i = blockIdx.x * blockDim.x + threadIdx.x;
    if (i >= NN * C1) return;
    int c = i & (C1 - 1);
    float x = g_h1[i] + bias[c];
    x = (x - bm[c]) * rsqrtf(bv[c] + BN_EPS) * bg[c] + bb[c];
    g_hm[i] = x > 0.f ? x : expm1f(x);
}

// ---------------- layer-2 edge logits (heads=1, 64 ch) -----------------------
__global__ void k_edge2(const int* __restrict__ ei, const float* __restrict__ att)
{
    int warp = (blockIdx.x * blockDim.x + threadIdx.x) >> 5;
    int lane = threadIdx.x & 31;
    if (warp >= ETOT) return;

    int src, dst;
    if (warp < EE) { src = ei[warp]; dst = ei[EE + warp]; }
    else           { src = dst = warp - EE; }

    int c = lane * 2;
    float2 a  = *(const float2*)&g_xl2[(size_t)src * HIDC + c];
    float2 b  = *(const float2*)&g_xr2[(size_t)dst * HIDC + c];
    float2 at = *(const float2*)&att[c];

    float s = at.x * lrelu(a.x + b.x) + at.y * lrelu(a.y + b.y);

    s += __shfl_xor_sync(0xffffffffu, s, 16);
    s += __shfl_xor_sync(0xffffffffu, s, 8);
    s += __shfl_xor_sync(0xffffffffu, s, 4);
    s += __shfl_xor_sync(0xffffffffu, s, 2);
    s += __shfl_xor_sync(0xffffffffu, s, 1);

    if (lane == 0) {
        float p = __expf(s);
        g_p2[warp] = p;
        atomicAdd(&g_sum2[dst], p);
    }
}

// ---------------- layer-2 weighted aggregation -------------------------------
__global__ void k_aggr2(const int* __restrict__ ei)
{
    int warp = (blockIdx.x * blockDim.x + threadIdx.x) >> 5;
    int lane = threadIdx.x & 31;
    if (warp >= ETOT) return;

    int src, dst;
    if (warp < EE) { src = ei[warp]; dst = ei[EE + warp]; }
    else           { src = dst = warp - EE; }

    float alpha = g_p2[warp] / g_sum2[dst];
    int c = lane * 2;
    float2 v = *(const float2*)&g_xl2[(size_t)src * HIDC + c];
    v.x *= alpha; v.y *= alpha;
    red_add_v2(&g_h2[(size_t)dst * HIDC + c], v);
}

// ---------------- final: +bias2, bn2, elu, classifier, sigmoid ---------------
__global__ void k_final(const float* __restrict__ bias,
                        const float* __restrict__ bg, const float* __restrict__ bb,
                        const float* __restrict__ bm, const float* __restrict__ bv,
                        const float* __restrict__ Wc, const float* __restrict__ bc,
                        float* __restrict__ out)
{
    int warp = (blockIdx.x * blockDim.x + threadIdx.x) >> 5;
    int lane = threadIdx.x & 31;
    if (warp >= NN) return;

    int c = lane * 2;
    float2 h  = *(const float2*)&g_h2[(size_t)warp * HIDC + c];
    float x0 = h.x + bias[c + 0];
    float x1 = h.y + bias[c + 1];
    x0 = (x0 - bm[c + 0]) * rsqrtf(bv[c + 0] + BN_EPS) * bg[c + 0] + bb[c + 0];
    x1 = (x1 - bm[c + 1]) * rsqrtf(bv[c + 1] + BN_EPS) * bg[c + 1] + bb[c + 1];
    x0 = x0 > 0.f ? x0 : expm1f(x0);
    x1 = x1 > 0.f ? x1 : expm1f(x1);

    float z = x0 * Wc[c + 0] + x1 * Wc[c + 1];
    z += __shfl_xor_sync(0xffffffffu, z, 16);
    z += __shfl_xor_sync(0xffffffffu, z, 8);
    z += __shfl_xor_sync(0xffffffffu, z, 4);
    z += __shfl_xor_sync(0xffffffffu, z, 2);
    z += __shfl_xor_sync(0xffffffffu, z, 1);

    if (lane == 0) {
        z += bc[0];
        out[warp] = 1.f / (1.f + __expf(-z));
    }
}

// ---------------- launch -----------------------------------------------------
extern "C" void kernel_launch(void* const* d_in, const int* in_sizes, int n_in,
                              void* d_out, int out_size)
{
    const float* x    = (const float*)d_in[0];
    const int*   ei   = (const int*)  d_in[1];
    const float* W1l  = (const float*)d_in[2];
    const float* b1l  = (const float*)d_in[3];
    const float* W1r  = (const float*)d_in[4];
    const float* b1r  = (const float*)d_in[5];
    const float* att1 = (const float*)d_in[6];
    const float* bias1= (const float*)d_in[7];
    const float* bn1g = (const float*)d_in[8];
    const float* bn1b = (const float*)d_in[9];
    const float* bn1m = (const float*)d_in[10];
    const float* bn1v = (const float*)d_in[11];
    const float* W2l  = (const float*)d_in[12];
    const float* b2l  = (const float*)d_in[13];
    const float* W2r  = (const float*)d_in[14];
    const float* b2r  = (const float*)d_in[15];
    const float* att2 = (const float*)d_in[16];
    const float* bias2= (const float*)d_in[17];
    const float* bn2g = (const float*)d_in[18];
    const float* bn2b = (const float*)d_in[19];
    const float* bn2m = (const float*)d_in[20];
    const float* bn2v = (const float*)d_in[21];
    const float* Wc   = (const float*)d_in[22];
    const float* bc   = (const float*)d_in[23];
    float* out = (float*)d_out;

    const int edgeBlocks = (ETOT * 32 + 255) / 256;   // warp per edge
    const int rowBlocks  = (NN + 31) / 32;

    k_zero<<<1024, 256>>>();

    // layer 1
    k_gemm1<<<rowBlocks, 2 * C1>>>(x, W1l, b1l, W1r, b1r);
    k_edge1<<<edgeBlocks, 256>>>(ei, att1);
    k_aggr1<<<edgeBlocks, 256>>>(ei);
    k_epi1<<<(NN * C1 + 255) / 256, 256>>>(bias1, bn1g, bn1b, bn1m, bn1v);

    // layer 2
    k_gemm2<<<rowBlocks, 2 * HIDC>>>(W2l, b2l, W2r, b2r);
    k_edge2<<<edgeBlocks, 256>>>(ei, att2);
    k_aggr2<<<edgeBlocks, 256>>>(ei);

    // epilogue + classifier
    k_final<<<(NN * 32 + 255) / 256, 256>>>(bias2, bn2g, bn2b, bn2m, bn2v, Wc, bc, out);
}

// round 3
// speedup vs baseline: 1.4265x; 1.4265x over previous
#include <cuda_runtime.h>
#include <cuda_bf16.h>
#include <cstdint>

#define NN      50000
#define EE      800000
#define ETOT    (EE + NN)        // edges + self loops
#define IN_CH   256
#define HIDC    64
#define HEADS   2
#define C1      (HEADS * HIDC)   // 128
#define BN_EPS  1e-5f

// ---------------- scratch (static device arrays; no allocation) --------------
__device__ float g_xl1[NN * C1];
__device__ float g_xr1[NN * C1];
__device__ float g_sum1[NN * HEADS];
__device__ float g_h1 [NN * C1];     // layer-1: accumulates sum(p * xl)
__device__ float g_hm [NN * C1];     // after bn1 + elu
__device__ float g_xl2[NN * HIDC];
__device__ float g_xr2[NN * HIDC];
__device__ float g_sum2[NN];
__device__ float g_h2 [NN * HIDC];   // layer-2: accumulates sum(p * xl)

// ---------------- helpers ----------------------------------------------------
__device__ __forceinline__ float lrelu(float v) { return v > 0.f ? v : 0.2f * v; }

__device__ __forceinline__ void red_add_v4(float* addr, float4 v) {
    asm volatile("red.global.add.v4.f32 [%0], {%1, %2, %3, %4};"
                 :: "l"(addr), "f"(v.x), "f"(v.y), "f"(v.z), "f"(v.w) : "memory");
}

// ---------------- zero accumulators (fresh every launch / graph replay) ------
__global__ void k_zero() {
    int i = blockIdx.x * blockDim.x + threadIdx.x;
    int stride = gridDim.x * blockDim.x;
    for (int j = i; j < NN * C1;    j += stride) g_h1[j]   = 0.f;
    for (int j = i; j < NN * HIDC;  j += stride) g_h2[j]   = 0.f;
    for (int j = i; j < NN * HEADS; j += stride) g_sum1[j] = 0.f;
    for (int j = i; j < NN;         j += stride) g_sum2[j] = 0.f;
}

// ---------------- dual GEMM: outl = X@Wl+bl, outr = X@Wr+br ------------------
template<int K, int M>
__device__ __forceinline__ void dual_gemm_body(
    const float* __restrict__ X,
    const float* __restrict__ Wl, const float* __restrict__ bl,
    const float* __restrict__ Wr, const float* __restrict__ br,
    float* __restrict__ outl, float* __restrict__ outr, int n)
{
    __shared__ float xs[32][K];
    const int t  = threadIdx.x;
    const int r0 = blockIdx.x * 32;

    // stage X tile (zero-pad OOB rows)
    for (int i = t * 4; i < 32 * K; i += 2 * M * 4) {
        int row = i / K, kk = i % K;
        float4 v = make_float4(0.f, 0.f, 0.f, 0.f);
        if (r0 + row < n) v = *(const float4*)&X[(size_t)(r0 + row) * K + kk];
        *(float4*)&xs[row][kk] = v;
    }
    __syncthreads();

    const int mat = t / M, col = t % M;
    const float* __restrict__ W = mat ? Wr : Wl;
    const float bias = mat ? br[col] : bl[col];

    float acc[32];
#pragma unroll
    for (int r = 0; r < 32; r++) acc[r] = 0.f;

    for (int k = 0; k < K; k += 4) {
        float w0 = W[(k + 0) * M + col];
        float w1 = W[(k + 1) * M + col];
        float w2 = W[(k + 2) * M + col];
        float w3 = W[(k + 3) * M + col];
#pragma unroll
        for (int r = 0; r < 32; r++) {
            float4 xv = *(const float4*)&xs[r][k];
            acc[r] = fmaf(xv.x, w0, acc[r]);
            acc[r] = fmaf(xv.y, w1, acc[r]);
            acc[r] = fmaf(xv.z, w2, acc[r]);
            acc[r] = fmaf(xv.w, w3, acc[r]);
        }
    }

    float* __restrict__ out = mat ? outr : outl;
#pragma unroll
    for (int r = 0; r < 32; r++)
        if (r0 + r < n) out[(size_t)(r0 + r) * M + col] = acc[r] + bias;
}

__global__ void k_gemm1(const float* __restrict__ X,
                        const float* __restrict__ Wl, const float* __restrict__ bl,
                        const float* __restrict__ Wr, const float* __restrict__ br)
{
    dual_gemm_body<IN_CH, C1>(X, Wl, bl, Wr, br, g_xl1, g_xr1, NN);
}

__global__ void k_gemm2(const float* __restrict__ Wl, const float* __restrict__ bl,
                        const float* __restrict__ Wr, const float* __restrict__ br)
{
    dual_gemm_body<C1, HIDC>(g_hm, Wl, bl, Wr, br, g_xl2, g_xr2, NN);
}

// ---------------- layer-1 FUSED edge pass ------------------------------------
// warp per edge; lane handles 4 channels of 128 (lanes 0-15 head0, 16-31 head1).
// Computes p = exp(logit) and directly accumulates p and p*xl into node
// accumulators; the softmax division happens in the epilogue:
//   out_i = (sum_j p_ij xl_j) / (sum_j p_ij).  Max-shift omitted (logits O(1)).
__global__ void k_edge1(const int* __restrict__ ei, const float* __restrict__ att)
{
    int warp = (blockIdx.x * blockDim.x + threadIdx.x) >> 5;
    int lane = threadIdx.x & 31;
    if (warp >= ETOT) return;

    int src, dst;
    if (warp < EE) { src = ei[warp]; dst = ei[EE + warp]; }
    else           { src = dst = warp - EE; }

    int c = lane * 4;
    float4 a  = *(const float4*)&g_xl1[(size_t)src * C1 + c];
    float4 b  = *(const float4*)&g_xr1[(size_t)dst * C1 + c];
    float4 at = *(const float4*)&att[c];   // att1 flattened [H*C] == channel idx

    float s = at.x * lrelu(a.x + b.x)
            + at.y * lrelu(a.y + b.y)
            + at.z * lrelu(a.z + b.z)
            + at.w * lrelu(a.w + b.w);

    // reduce within each 16-lane half (one head each); every lane gets its head's sum
    s += __shfl_xor_sync(0xffffffffu, s, 8);
    s += __shfl_xor_sync(0xffffffffu, s, 4);
    s += __shfl_xor_sync(0xffffffffu, s, 2);
    s += __shfl_xor_sync(0xffffffffu, s, 1);

    float p = __expf(s);

    if ((lane & 15) == 0)
        atomicAdd(&g_sum1[(size_t)dst * 2 + (lane >> 4)], p);

    float4 v = make_float4(a.x * p, a.y * p, a.z * p, a.w * p);
    red_add_v4(&g_h1[(size_t)dst * C1 + c], v);
}

// ---------------- layer-1 epilogue: /sum, +bias, bn, elu ---------------------
__global__ void k_epi1(const float* __restrict__ bias,
                       const float* __restrict__ bg, const float* __restrict__ bb,
                       const float* __restrict__ bm, const float* __restrict__ bv)
{
    int i = blockIdx.x * blockDim.x + threadIdx.x;
    if (i >= NN * C1) return;
    int c    = i & (C1 - 1);
    int node = i >> 7;                    // C1 == 128
    int h    = c >> 6;                    // head
    float x = g_h1[i] / g_sum1[node * 2 + h] + bias[c];
    x = (x - bm[c]) * rsqrtf(bv[c] + BN_EPS) * bg[c] + bb[c];
    g_hm[i] = x > 0.f ? x : expm1f(x);
}

// ---------------- layer-2 FUSED edge pass (heads=1, 64ch, 16 lanes/edge) -----
__global__ void k_edge2(const int* __restrict__ ei, const float* __restrict__ att)
{
    int gid  = blockIdx.x * blockDim.x + threadIdx.x;
    int e    = gid >> 4;                   // 16 lanes per edge
    int l    = gid & 15;
    if (e >= ETOT) return;

    int src, dst;
    if (e < EE) { src = ei[e]; dst = ei[EE + e]; }
    else        { src = dst = e - EE; }

    int c = l * 4;
    float4 a  = *(const float4*)&g_xl2[(size_t)src * HIDC + c];
    float4 b  = *(const float4*)&g_xr2[(size_t)dst * HIDC + c];
    float4 at = *(const float4*)&att[c];

    float s = at.x * lrelu(a.x + b.x)
            + at.y * lrelu(a.y + b.y)
            + at.z * lrelu(a.z + b.z)
            + at.w * lrelu(a.w + b.w);

    // reduce within 16-lane group; every lane gets full sum
    s += __shfl_xor_sync(0xffffffffu, s, 8);
    s += __shfl_xor_sync(0xffffffffu, s, 4);
    s += __shfl_xor_sync(0xffffffffu, s, 2);
    s += __shfl_xor_sync(0xffffffffu, s, 1);

    float p = __expf(s);

    if (l == 0)
        atomicAdd(&g_sum2[dst], p);

    float4 v = make_float4(a.x * p, a.y * p, a.z * p, a.w * p);
    red_add_v4(&g_h2[(size_t)dst * HIDC + c], v);
}

// ---------------- final: /sum, +bias2, bn2, elu, classifier, sigmoid ---------
__global__ void k_final(const float* __restrict__ bias,
                        const float* __restrict__ bg, const float* __restrict__ bb,
                        const float* __restrict__ bm, const float* __restrict__ bv,
                        const float* __restrict__ Wc, const float* __restrict__ bc,
                        float* __restrict__ out)
{
    int warp = (blockIdx.x * blockDim.x + threadIdx.x) >> 5;
    int lane = threadIdx.x & 31;
    if (warp >= NN) return;

    float inv_s = 1.f / g_sum2[warp];
    int c = lane * 2;
    float2 h  = *(const float2*)&g_h2[(size_t)warp * HIDC + c];
    float x0 = h.x * inv_s + bias[c + 0];
    float x1 = h.y * inv_s + bias[c + 1];
    x0 = (x0 - bm[c + 0]) * rsqrtf(bv[c + 0] + BN_EPS) * bg[c + 0] + bb[c + 0];
    x1 = (x1 - bm[c + 1]) * rsqrtf(bv[c + 1] + BN_EPS) * bg[c + 1] + bb[c + 1];
    x0 = x0 > 0.f ? x0 : expm1f(x0);
    x1 = x1 > 0.f ? x1 : expm1f(x1);

    float z = x0 * Wc[c + 0] + x1 * Wc[c + 1];
    z += __shfl_xor_sync(0xffffffffu, z, 16);
    z += __shfl_xor_sync(0xffffffffu, z, 8);
    z += __shfl_xor_sync(0xffffffffu, z, 4);
    z += __shfl_xor_sync(0xffffffffu, z, 2);
    z += __shfl_xor_sync(0xffffffffu, z, 1);

    if (lane == 0) {
        z += bc[0];
        out[warp] = 1.f / (1.f + __expf(-z));
    }
}

// ---------------- launch -----------------------------------------------------
extern "C" void kernel_launch(void* const* d_in, const int* in_sizes, int n_in,
                              void* d_out, int out_size)
{
    const float* x    = (const float*)d_in[0];
    const int*   ei   = (const int*)  d_in[1];
    const float* W1l  = (const float*)d_in[2];
    const float* b1l  = (const float*)d_in[3];
    const float* W1r  = (const float*)d_in[4];
    const float* b1r  = (const float*)d_in[5];
    const float* att1 = (const float*)d_in[6];
    const float* bias1= (const float*)d_in[7];
    const float* bn1g = (const float*)d_in[8];
    const float* bn1b = (const float*)d_in[9];
    const float* bn1m = (const float*)d_in[10];
    const float* bn1v = (const float*)d_in[11];
    const float* W2l  = (const float*)d_in[12];
    const float* b2l  = (const float*)d_in[13];
    const float* W2r  = (const float*)d_in[14];
    const float* b2r  = (const float*)d_in[15];
    const float* att2 = (const float*)d_in[16];
    const float* bias2= (const float*)d_in[17];
    const float* bn2g = (const float*)d_in[18];
    const float* bn2b = (const float*)d_in[19];
    const float* bn2m = (const float*)d_in[20];
    const float* bn2v = (const float*)d_in[21];
    const float* Wc   = (const float*)d_in[22];
    const float* bc   = (const float*)d_in[23];
    float* out = (float*)d_out;

    const int edge1Blocks = (ETOT * 32 + 255) / 256;   // warp per edge
    const int edge2Blocks = (ETOT * 16 + 255) / 256;   // 16 lanes per edge
    const int rowBlocks   = (NN + 31) / 32;

    k_zero<<<1024, 256>>>();

    // layer 1
    k_gemm1<<<rowBlocks, 2 * C1>>>(x, W1l, b1l, W1r, b1r);
    k_edge1<<<edge1Blocks, 256>>>(ei, att1);
    k_epi1<<<(NN * C1 + 255) / 256, 256>>>(bias1, bn1g, bn1b, bn1m, bn1v);

    // layer 2
    k_gemm2<<<rowBlocks, 2 * HIDC>>>(W2l, b2l, W2r, b2r);
    k_edge2<<<edge2Blocks, 256>>>(ei, att2);

    // epilogue + classifier
    k_final<<<(NN * 32 + 255) / 256, 256>>>(bias2, bn2g, bn2b, bn2m, bn2v, Wc, bc, out);
}

// round 4
// speedup vs baseline: 1.5656x; 1.0975x over previous
#include <cuda_runtime.h>
#include <cuda_bf16.h>
#include <cstdint>

#define NN      50000
#define EE      800000
#define ETOT    (EE + NN)        // edges + self loops
#define IN_CH   256
#define HIDC    64
#define HEADS   2
#define C1      (HEADS * HIDC)   // 128
#define BN_EPS  1e-5f

// ---------------- scratch (static device arrays; no allocation) --------------
// All zero-initialized at module load; every launch restores the zero state
// of the accumulators after consuming them (graph-replay safe, race-free).
__device__ float g_xl1[NN * C1];
__device__ float g_xr1[NN * C1];
__device__ float g_sum1[NN * HEADS];
__device__ float g_h1 [NN * C1];     // layer-1: accumulates sum(p * xl)
__device__ float g_hm [NN * C1];     // after bn1 + elu
__device__ float g_xl2[NN * HIDC];
__device__ float g_xr2[NN * HIDC];
__device__ float g_sum2[NN];
__device__ float g_h2 [NN * HIDC];   // layer-2: accumulates sum(p * xl)

// ---------------- helpers ----------------------------------------------------
__device__ __forceinline__ float lrelu(float v) { return v > 0.f ? v : 0.2f * v; }

__device__ __forceinline__ void red_add_v4(float* addr, float4 v) {
    asm volatile("red.global.add.v4.f32 [%0], {%1, %2, %3, %4};"
                 :: "l"(addr), "f"(v.x), "f"(v.y), "f"(v.z), "f"(v.w) : "memory");
}

// packed f32x2 helpers (FFMA2 — only reachable via PTX on sm_103a)
__device__ __forceinline__ unsigned long long bcast2(float w) {
    unsigned long long r;
    asm("mov.b64 %0, {%1, %1};" : "=l"(r) : "f"(w));
    return r;
}
__device__ __forceinline__ void ffma2(unsigned long long& acc,
                                      unsigned long long a, unsigned long long b) {
    asm("fma.rn.f32x2 %0, %1, %2, %0;" : "+l"(acc) : "l"(a), "l"(b));
}
__device__ __forceinline__ float2 unpack2(unsigned long long v) {
    float lo, hi;
    asm("mov.b64 {%0, %1}, %2;" : "=f"(lo), "=f"(hi) : "l"(v));
    return make_float2(lo, hi);
}

// ---------------- dual GEMM with packed f32x2 FMA ----------------------------
// Tile: 32 rows x 2M cols (cols [0,M) -> Wl, [M,2M) -> Wr). blockDim = M.
// Thread t owns 2 adjacent cols (2t, 2t+1), always within one matrix.
// X tile staged k-major in smem (pad 36: conflict-free stores, aligned
// float2 row-pair loads, broadcast across the warp).
template<int K, int M>
__device__ __forceinline__ void dual_gemm_f32x2(
    const float* __restrict__ X,
    const float* __restrict__ Wl, const float* __restrict__ bl,
    const float* __restrict__ Wr, const float* __restrict__ br,
    float* __restrict__ outl, float* __restrict__ outr, int n)
{
    constexpr int PAD = 36;
    __shared__ __align__(16) float xs[K * PAD];   // xs[k*PAD + row]
    const int t  = threadIdx.x;                   // 0..M-1
    const int r0 = blockIdx.x * 32;

    // stage X tile transposed (zero-pad OOB rows)
    for (int i = t * 4; i < 32 * K; i += M * 4) {
        int row = i / K, kk = i % K;
        float4 v = make_float4(0.f, 0.f, 0.f, 0.f);
        if (r0 + row < n) v = *(const float4*)&X[(size_t)(r0 + row) * K + kk];
        xs[(kk + 0) * PAD + row] = v.x;
        xs[(kk + 1) * PAD + row] = v.y;
        xs[(kk + 2) * PAD + row] = v.z;
        xs[(kk + 3) * PAD + row] = v.w;
    }
    __syncthreads();

    const int c0  = 2 * t;
    const int mat = (c0 >= M) ? 1 : 0;
    const float* __restrict__ W  = mat ? Wr : Wl;
    const float* __restrict__ bs = mat ? br : bl;
    const int wc = c0 & (M - 1);

    unsigned long long accA[16], accB[16];       // row-pairs for col wc, wc+1
#pragma unroll
    for (int r = 0; r < 16; r++) { accA[r] = 0ULL; accB[r] = 0ULL; }

#pragma unroll 4
    for (int k = 0; k < K; k++) {
        float2 w = *(const float2*)&W[k * M + wc];
        unsigned long long wA = bcast2(w.x);
        unsigned long long wB = bcast2(w.y);
        const unsigned long long* xrow = (const unsigned long long*)&xs[k * PAD];
#pragma unroll
        for (int r = 0; r < 16; r++) {
            unsigned long long xv = xrow[r];     // rows 2r,2r+1 (broadcast LDS)
            ffma2(accA[r], xv, wA);
            ffma2(accB[r], xv, wB);
        }
    }

    float* __restrict__ out = mat ? outr : outl;
    const float b0 = bs[wc], b1 = bs[wc + 1];
#pragma unroll
    for (int r = 0; r < 16; r++) {
        float2 a = unpack2(accA[r]);
        float2 b = unpack2(accB[r]);
        int row = r0 + 2 * r;
        if (row < n) {
            out[(size_t)row * M + wc]     = a.x + b0;
            out[(size_t)row * M + wc + 1] = b.x + b1;
        }
        if (row + 1 < n) {
            out[(size_t)(row + 1) * M + wc]     = a.y + b0;
            out[(size_t)(row + 1) * M + wc + 1] = b.y + b1;
        }
    }
}

__global__ void k_gemm1(const float* __restrict__ X,
                        const float* __restrict__ Wl, const float* __restrict__ bl,
                        const float* __restrict__ Wr, const float* __restrict__ br)
{
    dual_gemm_f32x2<IN_CH, C1>(X, Wl, bl, Wr, br, g_xl1, g_xr1, NN);
}

// gemm2 also re-zeros g_sum1 (consumed by k_epi1, which runs just before this;
// next reader is edge1 of the NEXT launch, so this is race-free).
__global__ void k_gemm2(const float* __restrict__ Wl, const float* __restrict__ bl,
                        const float* __restrict__ Wr, const float* __restrict__ br)
{
    int gid = blockIdx.x * blockDim.x + threadIdx.x;
    if (gid < NN * HEADS) g_sum1[gid] = 0.f;
    dual_gemm_f32x2<C1, HIDC>(g_hm, Wl, bl, Wr, br, g_xl2, g_xr2, NN);
}

// ---------------- layer-1 FUSED edge pass ------------------------------------
// warp per edge; lane handles 4 channels of 128 (lanes 0-15 head0, 16-31 head1).
// Accumulates p and p*xl; softmax division deferred to the epilogue.
__global__ void k_edge1(const int* __restrict__ ei, const float* __restrict__ att)
{
    int warp = (blockIdx.x * blockDim.x + threadIdx.x) >> 5;
    int lane = threadIdx.x & 31;
    if (warp >= ETOT) return;

    int src, dst;
    if (warp < EE) { src = ei[warp]; dst = ei[EE + warp]; }
    else           { src = dst = warp - EE; }

    int c = lane * 4;
    float4 a  = *(const float4*)&g_xl1[(size_t)src * C1 + c];
    float4 b  = *(const float4*)&g_xr1[(size_t)dst * C1 + c];
    float4 at = *(const float4*)&att[c];

    float s = at.x * lrelu(a.x + b.x)
            + at.y * lrelu(a.y + b.y)
            + at.z * lrelu(a.z + b.z)
            + at.w * lrelu(a.w + b.w);

    s += __shfl_xor_sync(0xffffffffu, s, 8);
    s += __shfl_xor_sync(0xffffffffu, s, 4);
    s += __shfl_xor_sync(0xffffffffu, s, 2);
    s += __shfl_xor_sync(0xffffffffu, s, 1);

    float p = __expf(s);

    if ((lane & 15) == 0)
        atomicAdd(&g_sum1[(size_t)dst * 2 + (lane >> 4)], p);

    float4 v = make_float4(a.x * p, a.y * p, a.z * p, a.w * p);
    red_add_v4(&g_h1[(size_t)dst * C1 + c], v);
}

// ---------------- layer-1 epilogue: /sum, +bias, bn, elu (float4) ------------
// Also restores g_h1 to zero for the next graph replay (single reader per elem).
__global__ void k_epi1(const float* __restrict__ bias,
                       const float* __restrict__ bg, const float* __restrict__ bb,
                       const float* __restrict__ bm, const float* __restrict__ bv)
{
    int i4 = (blockIdx.x * blockDim.x + threadIdx.x) * 4;
    if (i4 >= NN * C1) return;
    int c    = i4 & (C1 - 1);
    int node = i4 >> 7;                   // C1 == 128
    int h    = c >> 6;                    // 4-ch group never crosses head bound
    float inv_s = __fdividef(1.f, g_sum1[node * 2 + h]);

    float4 hv = *(const float4*)&g_h1[i4];
    float4 bi = *(const float4*)&bias[c];
    float4 gm = *(const float4*)&bg[c];
    float4 bt = *(const float4*)&bb[c];
    float4 mu = *(const float4*)&bm[c];
    float4 vr = *(const float4*)&bv[c];

    float x0 = (hv.x * inv_s + bi.x - mu.x) * rsqrtf(vr.x + BN_EPS) * gm.x + bt.x;
    float x1 = (hv.y * inv_s + bi.y - mu.y) * rsqrtf(vr.y + BN_EPS) * gm.y + bt.y;
    float x2 = (hv.z * inv_s + bi.z - mu.z) * rsqrtf(vr.z + BN_EPS) * gm.z + bt.z;
    float x3 = (hv.w * inv_s + bi.w - mu.w) * rsqrtf(vr.w + BN_EPS) * gm.w + bt.w;

    float4 o;
    o.x = x0 > 0.f ? x0 : expm1f(x0);
    o.y = x1 > 0.f ? x1 : expm1f(x1);
    o.z = x2 > 0.f ? x2 : expm1f(x2);
    o.w = x3 > 0.f ? x3 : expm1f(x3);
    *(float4*)&g_hm[i4] = o;
    *(float4*)&g_h1[i4] = make_float4(0.f, 0.f, 0.f, 0.f);
}

// ---------------- layer-2 FUSED edge pass (heads=1, 64ch, 16 lanes/edge) -----
__global__ void k_edge2(const int* __restrict__ ei, const float* __restrict__ att)
{
    int gid  = blockIdx.x * blockDim.x + threadIdx.x;
    int e    = gid >> 4;                   // 16 lanes per edge
    int l    = gid & 15;
    if (e >= ETOT) return;

    int src, dst;
    if (e < EE) { src = ei[e]; dst = ei[EE + e]; }
    else        { src = dst = e - EE; }

    int c = l * 4;
    float4 a  = *(const float4*)&g_xl2[(size_t)src * HIDC + c];
    float4 b  = *(const float4*)&g_xr2[(size_t)dst * HIDC + c];
    float4 at = *(const float4*)&att[c];

    float s = at.x * lrelu(a.x + b.x)
            + at.y * lrelu(a.y + b.y)
            + at.z * lrelu(a.z + b.z)
            + at.w * lrelu(a.w + b.w);

    s += __shfl_xor_sync(0xffffffffu, s, 8);
    s += __shfl_xor_sync(0xffffffffu, s, 4);
    s += __shfl_xor_sync(0xffffffffu, s, 2);
    s += __shfl_xor_sync(0xffffffffu, s, 1);

    float p = __expf(s);

    if (l == 0)
        atomicAdd(&g_sum2[dst], p);

    float4 v = make_float4(a.x * p, a.y * p, a.z * p, a.w * p);
    red_add_v4(&g_h2[(size_t)dst * HIDC + c], v);
}

// ---------------- final: /sum, +bias2, bn2, elu, classifier, sigmoid ---------
// Also restores g_h2 / g_sum2 to zero (warp-private accesses, program order
// guarantees the reads precede the zeroing stores within each warp).
__global__ void k_final(const float* __restrict__ bias,
                        const float* __restrict__ bg, const float* __restrict__ bb,
                        const float* __restrict__ bm, const float* __restrict__ bv,
                        const float* __restrict__ Wc, const float* __restrict__ bc,
                        float* __restrict__ out)
{
    int warp = (blockIdx.x * blockDim.x + threadIdx.x) >> 5;
    int lane = threadIdx.x & 31;
    if (warp >= NN) return;

    float inv_s = __fdividef(1.f, g_sum2[warp]);
    int c = lane * 2;
    float2 h  = *(const float2*)&g_h2[(size_t)warp * HIDC + c];
    float x0 = h.x * inv_s + bias[c + 0];
    float x1 = h.y * inv_s + bias[c + 1];
    x0 = (x0 - bm[c + 0]) * rsqrtf(bv[c + 0] + BN_EPS) * bg[c + 0] + bb[c + 0];
    x1 = (x1 - bm[c + 1]) * rsqrtf(bv[c + 1] + BN_EPS) * bg[c + 1] + bb[c + 1];
    x0 = x0 > 0.f ? x0 : expm1f(x0);
    x1 = x1 > 0.f ? x1 : expm1f(x1);

    // restore zero state for next replay
    *(float2*)&g_h2[(size_t)warp * HIDC + c] = make_float2(0.f, 0.f);
    if (lane == 0) g_sum2[warp] = 0.f;

    float z = x0 * Wc[c + 0] + x1 * Wc[c + 1];
    z += __shfl_xor_sync(0xffffffffu, z, 16);
    z += __shfl_xor_sync(0xffffffffu, z, 8);
    z += __shfl_xor_sync(0xffffffffu, z, 4);
    z += __shfl_xor_sync(0xffffffffu, z, 2);
    z += __shfl_xor_sync(0xffffffffu, z, 1);

    if (lane == 0) {
        z += bc[0];
        out[warp] = 1.f / (1.f + __expf(-z));
    }
}

// ---------------- launch -----------------------------------------------------
extern "C" void kernel_launch(void* const* d_in, const int* in_sizes, int n_in,
                              void* d_out, int out_size)
{
    const float* x    = (const float*)d_in[0];
    const int*   ei   = (const int*)  d_in[1];
    const float* W1l  = (const float*)d_in[2];
    const float* b1l  = (const float*)d_in[3];
    const float* W1r  = (const float*)d_in[4];
    const float* b1r  = (const float*)d_in[5];
    const float* att1 = (const float*)d_in[6];
    const float* bias1= (const float*)d_in[7];
    const float* bn1g = (const float*)d_in[8];
    const float* bn1b = (const float*)d_in[9];
    const float* bn1m = (const float*)d_in[10];
    const float* bn1v = (const float*)d_in[11];
    const float* W2l  = (const float*)d_in[12];
    const float* b2l  = (const float*)d_in[13];
    const float* W2r  = (const float*)d_in[14];
    const float* b2r  = (const float*)d_in[15];
    const float* att2 = (const float*)d_in[16];
    const float* bias2= (const float*)d_in[17];
    const float* bn2g = (const float*)d_in[18];
    const float* bn2b = (const float*)d_in[19];
    const float* bn2m = (const float*)d_in[20];
    const float* bn2v = (const float*)d_in[21];
    const float* Wc   = (const float*)d_in[22];
    const float* bc   = (const float*)d_in[23];
    float* out = (float*)d_out;

    const int edge1Blocks = (ETOT * 32 + 255) / 256;   // warp per edge
    const int edge2Blocks = (ETOT * 16 + 255) / 256;   // 16 lanes per edge
    const int rowBlocks   = (NN + 31) / 32;

    // layer 1
    k_gemm1<<<rowBlocks, C1>>>(x, W1l, b1l, W1r, b1r);
    k_edge1<<<edge1Blocks, 256>>>(ei, att1);
    k_epi1<<<(NN * C1 / 4 + 255) / 256, 256>>>(bias1, bn1g, bn1b, bn1m, bn1v);

    // layer 2
    k_gemm2<<<rowBlocks, HIDC>>>(W2l, b2l, W2r, b2r);
    k_edge2<<<edge2Blocks, 256>>>(ei, att2);

    // epilogue + classifier
    k_final<<<(NN * 32 + 255) / 256, 256>>>(bias2, bn2g, bn2b, bn2m, bn2v, Wc, bc, out);
}